// round 15
// baseline (speedup 1.0000x reference)
#include <cuda_runtime.h>
#include <math.h>
#include <float.h>

namespace {
constexpr int B_ = 64;    // batch
constexpr int S_ = 128;   // seq len
constexpr int D_ = 128;   // embed dim
constexpr int V_ = 512;   // vocab
constexpr int N_ = 256;   // memory slots
constexpr int M_ = 64;    // memory width
constexpr int PITCH = 65; // smem pitch for mem (bank-conflict-free)
constexpr int T_ = 512;   // threads per CTA (16 warps)

constexpr int SMEM_FLOATS =
    N_ * PITCH   // mem 16640
    + 512        // xin
    + 1024       // xo[2][512]
    + 4096       // part
    + 4096       // pcl
    + 1024       // bias
    + 512        // obv
    + 256        // hb
    + 256 + 256  // wprev, wga
    + 192        // keys, er, ad
    + 256        // rvp
    + 16 + 8;    // red, sc
constexpr size_t SMEM_BYTES = SMEM_FLOATS * sizeof(float);
}

// fp32 transposed weights (static device scratch; no allocation)
__device__ float g_lstmT[448 * 1024];  // [k][gate-row]; k = [emb|rv|h]
__device__ float g_headsT[256 * 256];  // [k][ho], ho >= 198 zero-padded
__device__ float g_outT[320 * 512];    // [k][vocab-row]

__global__ void prep_kernel(
    const float* __restrict__ W_ih, const float* __restrict__ W_hh,
    const float* __restrict__ key_W, const float* __restrict__ erase_W,
    const float* __restrict__ add_W, const float* __restrict__ beta_W,
    const float* __restrict__ gate_W, const float* __restrict__ gamma_W,
    const float* __restrict__ shift_W, const float* __restrict__ out_W)
{
    const int stride = blockDim.x * gridDim.x;
    const int t0 = blockIdx.x * blockDim.x + threadIdx.x;
    for (int i = t0; i < 448 * 1024; i += stride) {
        const int k = i >> 10, row = i & 1023;
        g_lstmT[i] = (k < 192) ? W_ih[row * 192 + k] : W_hh[row * 256 + (k - 192)];
    }
    for (int i = t0; i < 256 * 256; i += stride) {
        const int k = i >> 8, ho = i & 255;
        float v = 0.0f;
        if (ho < 64)        v = key_W[ho * 256 + k];
        else if (ho < 128)  v = erase_W[(ho - 64) * 256 + k];
        else if (ho < 192)  v = add_W[(ho - 128) * 256 + k];
        else if (ho == 192) v = beta_W[k];
        else if (ho == 193) v = gate_W[k];
        else if (ho == 194) v = gamma_W[k];
        else if (ho < 198)  v = shift_W[(ho - 195) * 256 + k];
        g_headsT[i] = v;
    }
    for (int i = t0; i < 320 * 512; i += stride) {
        const int k = i >> 9, row = i & 511;
        g_outT[i] = out_W[row * 320 + k];
    }
}

__device__ __forceinline__ float sigm_f(float x) {
    return __fdividef(1.0f, 1.0f + __expf(-x));
}
__device__ __forceinline__ float tanh_f(float x) {
    return __fdividef(2.0f, 1.0f + __expf(-2.0f * x)) - 1.0f;
}
__device__ __forceinline__ float softplus_(float x) { return log1pf(expf(x)); }

__device__ __forceinline__ void fma4(float4& a, float s, const float4 w) {
    a.x = fmaf(s, w.x, a.x); a.y = fmaf(s, w.y, a.y);
    a.z = fmaf(s, w.z, a.z); a.w = fmaf(s, w.w, a.w);
}

__device__ __forceinline__ float rsum(float v) {
#pragma unroll
    for (int o = 16; o; o >>= 1) v += __shfl_xor_sync(0xffffffffu, v, o);
    return v;
}

__device__ __forceinline__ void cluster_sync_() {
    asm volatile("barrier.cluster.arrive.aligned;" ::: "memory");
    asm volatile("barrier.cluster.wait.aligned;" ::: "memory");
}
// store v into CTA `dst` smem at the same offset as local pointer p
__device__ __forceinline__ void st_peer(float* p, unsigned dst, float v) {
    unsigned a = (unsigned)__cvta_generic_to_shared(p);
    unsigned ra;
    asm volatile("mapa.shared::cluster.u32 %0, %1, %2;" : "=r"(ra) : "r"(a), "r"(dst));
    asm volatile("st.shared::cluster.f32 [%0], %1;" :: "r"(ra), "f"(v) : "memory");
}

// named barrier for warps 0-7 only (256 threads)
__device__ __forceinline__ void bar8() {
    asm volatile("bar.sync 1, 256;" ::: "memory");
}
// sum over warps 0-7 (must be called by all 256 threads of warps 0-7)
__device__ __forceinline__ float sum8(float v, float* red) {
    v = rsum(v);
    bar8();
    if ((threadIdx.x & 31) == 0) red[threadIdx.x >> 5] = v;
    bar8();
    float s = red[0];
#pragma unroll
    for (int i = 1; i < 8; ++i) s += red[i];
    return s;
}

__global__ void __launch_bounds__(T_, 1) __cluster_dims__(4, 1, 1) ntm_kernel(
    const int* __restrict__ x, const float* __restrict__ emb,
    const float* __restrict__ b_ih, const float* __restrict__ b_hh,
    const float* __restrict__ key_b, const float* __restrict__ beta_b,
    const float* __restrict__ gate_b, const float* __restrict__ shift_b,
    const float* __restrict__ gamma_b, const float* __restrict__ erase_b,
    const float* __restrict__ add_b, const float* __restrict__ out_b,
    const float* __restrict__ mem_init, float* __restrict__ out)
{
    extern __shared__ float sm[];
    const int tid = threadIdx.x;
    const int lane = tid & 31;
    const int wi = tid >> 5;            // warp 0..15
    const int bpair = blockIdx.x >> 2;  // cluster index: 2 batch elements
    unsigned rank;
    asm("mov.u32 %0, %%cluster_ctarank;" : "=r"(rank));
    const int rk = (int)rank;           // 0..3
    const int cb = rk >> 1;             // my batch within pair (0/1)
    const unsigned partner = rank ^ 2u; // same j-slice, other batch pair
    const int gb_m = bpair * 2 + cb;
    const int gb_o = bpair * 2 + (1 - cb);

    float* mem   = sm;                 // [N_][PITCH]
    float* xin   = mem + N_ * PITCH;   // 512
    float* xo    = xin + 512;          // [2][512]
    float* part  = xo + 1024;          // 4096
    float* pcl   = part + 4096;        // 4096 [src rank][1024]
    float* bias  = pcl + 4096;         // 1024
    float* obv   = bias + 1024;        // 512
    float* hb    = obv + 512;          // 256
    float* wprev = hb + 256;           // 256
    float* wga   = wprev + N_;         // 256
    float* keys  = wga + N_;           // 64
    float* er    = keys + M_;          // 64
    float* ad    = er + M_;            // 64
    float* rvp   = ad + M_;            // 256
    float* red   = rvp + 256;          // 16
    float* sc    = red + 16;           // 8: beta,gate,gamma,knorm,sh0..2

    // ---- init state & cached biases ----
    for (int i = tid; i < N_ * M_; i += T_)
        mem[(i >> 6) * PITCH + (i & 63)] = mem_init[(size_t)gb_m * N_ * M_ + i];
    bias[tid]       = b_ih[tid]       + b_hh[tid];
    bias[512 + tid] = b_ih[512 + tid] + b_hh[512 + tid];
    obv[tid] = out_b[tid];
    xo[tid] = 0.0f; xo[512 + tid] = 0.0f;
    if (tid < 256) {
        float v = 0.0f;
        if (tid < 64)        v = key_b[tid];
        else if (tid < 128)  v = erase_b[tid - 64];
        else if (tid < 192)  v = add_b[tid - 128];
        else if (tid == 192) v = beta_b[0];
        else if (tid == 193) v = gate_b[0];
        else if (tid == 194) v = gamma_b[0];
        else if (tid < 198)  v = shift_b[tid - 195];
        hb[tid] = v;
    }
    if (tid < 256) { xin[192 + tid] = 0.0f; wprev[tid] = 0.0f; }
    if (tid < 64)  { xin[448 + tid] = 0.0f; xin[128 + tid] = 0.0f; }
    float c_reg = 0.0f;                 // valid for tid < 256
    __syncthreads();
    cluster_sync_();   // xo zero-init complete before any peer traffic

    for (int t = 0; t < S_; ++t) {
        float* xot = xo + ((t & 1) << 9);
        float* xon = xo + (((t + 1) & 1) << 9);

        // ---- phase 0: emb loads + own rv copy ----
        const int tok_m = x[gb_m * S_ + t];
        const int tok_o = x[gb_o * S_ + t];
        if (tid < 128)      { xin[tid] = emb[(size_t)tok_m * D_ + tid];
                              xot[tid] = emb[(size_t)tok_o * D_ + tid]; }
        else if (tid < 192)  xin[tid] = xin[tid + 320];
        __syncthreads();

        // ---- phase 1: LSTM preacts, k-quarter per CTA, both batches ----
        {
            const int jb = wi & 7, ks = wi >> 3;
            const int k0 = rk * 112 + ks * 56;
            const int j = jb * 128 + (lane << 2);
            const float* wt = g_lstmT + (size_t)k0 * 1024 + j;
            const float* xm = xin + k0;
            const float* xq = xot + k0;
            float4 am = make_float4(0, 0, 0, 0), ao = am;
#pragma unroll 4
            for (int k = 0; k < 56; ++k) {
                const float4 w = *(const float4*)(wt + (size_t)k * 1024);
                fma4(am, xm[k], w);
                fma4(ao, xq[k], w);
            }
            ((float4*)(part + ks * 2048 + jb * 128))[lane] = am;
            ((float4*)(part + ks * 2048 + 1024 + jb * 128))[lane] = ao;
        }
        __syncthreads();
#pragma unroll
        for (int i = 0; i < 4; ++i) {
            const int idx = i * 512 + tid;
            const int bt = idx >> 10, j2 = idx & 1023;
            const float v = part[bt * 1024 + j2] + part[2048 + bt * 1024 + j2];
            const int db = (bt == 0) ? (rk & 2) : ((rk ^ 2) & 2);
            float* dst = &pcl[rk * 1024 + j2];
            if (db == rk)     *dst = v; else st_peer(dst, (unsigned)db, v);
            if (db + 1 == rk) *dst = v; else st_peer(dst, (unsigned)(db + 1), v);
        }
        cluster_sync_();   // sync A: pcl complete everywhere

        // ---- cell update (tid < 256; torch order i,f,g,o) + h push ----
        if (tid < 256) {
            float s0 = 0.f, s1 = 0.f, s2 = 0.f, s3 = 0.f;
#pragma unroll
            for (int r = 0; r < 4; ++r) {
                const float* p = pcl + r * 1024;
                s0 += p[tid]; s1 += p[256 + tid];
                s2 += p[512 + tid]; s3 += p[768 + tid];
            }
            const float ig = sigm_f(s0 + bias[tid]);
            const float fg = sigm_f(s1 + bias[256 + tid]);
            const float gg = tanh_f(s2 + bias[512 + tid]);
            const float og = sigm_f(s3 + bias[768 + tid]);
            c_reg = fg * c_reg + ig * gg;
            const float hv = og * tanh_f(c_reg);
            xin[192 + tid] = hv;
            st_peer(&xot[192 + tid], partner, hv);
            st_peer(&xon[192 + tid], partner, hv);
        }
        cluster_sync_();   // sync B1: h_t visible everywhere

        // ---- phase 2: heads, ho-slice per CTA, both batches ----
        {
            const int kg0 = wi * 16;
            float2 am = make_float2(0, 0), ao = am;
            const float* xm = xin + 192 + kg0;
            const float* xq = xot + 192 + kg0;
#pragma unroll
            for (int k = 0; k < 16; ++k) {
                const float2 w = *(const float2*)(g_headsT
                    + (size_t)(kg0 + k) * 256 + rk * 64 + lane * 2);
                am.x = fmaf(xm[k], w.x, am.x); am.y = fmaf(xm[k], w.y, am.y);
                ao.x = fmaf(xq[k], w.x, ao.x); ao.y = fmaf(xq[k], w.y, ao.y);
            }
            ((float2*)(part + wi * 128))[lane] = am;
            ((float2*)(part + wi * 128 + 64))[lane] = ao;
        }
        __syncthreads();
        if (tid < 128) {
            const int bt = tid >> 6, hol = tid & 63;
            float d = 0.0f;
#pragma unroll
            for (int kc = 0; kc < 16; ++kc) d += part[kc * 128 + bt * 64 + hol];
            const int ho = rk * 64 + hol;
            d += hb[ho];
            float* dst = nullptr; float val = 0.0f;
            if (ho < 64)        { dst = &keys[ho];         val = d; }
            else if (ho < 128)  { dst = &er[ho - 64];      val = sigm_f(d); }
            else if (ho < 192)  { dst = &ad[ho - 128];     val = tanh_f(d); }
            else if (ho == 192) { dst = &sc[0];            val = softplus_(d); }
            else if (ho == 193) { dst = &sc[1];            val = sigm_f(d); }
            else if (ho == 194) { dst = &sc[2];            val = 1.0f + softplus_(d); }
            else if (ho < 198)  { dst = &sc[4 + ho - 195]; val = d; }
            if (dst) {
                const int db = (bt == 0) ? (rk & 2) : ((rk ^ 2) & 2);
                if (db == rk)     *dst = val; else st_peer(dst, (unsigned)db, val);
                if (db + 1 == rk) *dst = val; else st_peer(dst, (unsigned)(db + 1), val);
            }
        }
        cluster_sync_();   // sync B: keys/er/ad/sc complete everywhere

        // ---- phase 3: shift softmax (t0) + key norm (warp 1) ----
        if (tid == 0) {
            const float s0 = sc[4], s1 = sc[5], s2 = sc[6];
            const float mx = fmaxf(s0, fmaxf(s1, s2));
            const float e0 = __expf(s0 - mx), e1 = __expf(s1 - mx), e2 = __expf(s2 - mx);
            const float inv = __fdividef(1.0f, e0 + e1 + e2);
            sc[4] = e0 * inv; sc[5] = e1 * inv; sc[6] = e2 * inv;
        } else if (tid >= 32 && tid < 64) {
            const int l = tid - 32;
            float v = keys[l] * keys[l] + keys[l + 32] * keys[l + 32];
#pragma unroll
            for (int o = 16; o; o >>= 1) v += __shfl_xor_sync(0xffffffffu, v, o);
            if (l == 0) sc[3] = fmaxf(sqrtf(v), 1e-12f);
        }
        __syncthreads();

        // ==== SPLIT: warps 0-7 addressing pipeline; warps 8-15 out-proj h-part ====
        if (wi < 8) {
            const float beta = sc[0], gatev = sc[1], gammav = sc[2], knorm = sc[3];
            const float sh0 = sc[4], sh1 = sc[5], sh2 = sc[6];

            // phase 4: content addressing, 1 thread per slot
            {
                const float* mrow = mem + tid * PITCH;
                float dot = 0.0f, sq = 0.0f;
#pragma unroll 8
                for (int j = 0; j < 64; ++j) {
                    const float v = mrow[j];
                    dot += v * keys[j];
                    sq += v * v;
                }
                const float sim = __fdividef(dot, fmaxf(sqrtf(sq), 1e-12f) * knorm);
                const float e = __expf(beta * sim);
                const float ssum = sum8(e, red);
                const float wc = __fdividef(e, ssum);
                wga[tid] = gatev * wc + (1.0f - gatev) * wprev[tid];
            }
            bar8();   // wga(w_g) visible to warps 0-7

            // phase 5: circular conv + sharpening
            {
                const float wt_ = sh0 * wga[(tid + 1) & 255] + sh1 * wga[tid]
                                + sh2 * wga[(tid + 255) & 255];
                const float ws = __powf(wt_, gammav);
                const float wsum = sum8(ws, red);   // entry bar fences conv reads
                const float w = __fdividef(ws, wsum);
                wprev[tid] = w;
                wga[tid] = w;
            }
            bar8();   // final w visible

            // phase 6: rv = w @ mem (4 n-groups x 64 m on 256 threads)
            {
                const int m = tid & 63, g = tid >> 6;
                const float* base = mem + (g * 64) * PITCH + m;
                const float* wp = wga + g * 64;
                float s = 0.0f;
#pragma unroll 8
                for (int n = 0; n < 64; ++n) s += wp[n] * base[n * PITCH];
                rvp[tid] = s;
            }
            bar8();
            if (tid < 64) {
                const float r_ = (rvp[tid] + rvp[64 + tid])
                               + (rvp[128 + tid] + rvp[192 + tid]);
                xin[448 + tid] = r_;
                st_peer(&xot[448 + tid], partner, r_);  // rv_t for peer phase 8
                st_peer(&xon[128 + tid], partner, r_);  // rv_t for peer LSTM t+1
            }
        } else {
            // out-proj h-part: k = 0..255, both batches; warp wo = wi-8 owns 32 k
            const int wo = wi - 8;
            const int k0 = wo * 32;
            const int j4 = rk * 128 + (lane << 2);
            const float* wt = g_outT + (size_t)k0 * 512 + j4;
            const float* xm = xin + 192 + k0;
            const float* xq = xot + 192 + k0;
            float4 am = make_float4(0, 0, 0, 0), ao = am;
#pragma unroll 4
            for (int k = 0; k < 32; ++k) {
                const float4 w = *(const float4*)(wt + (size_t)k * 512);
                fma4(am, xm[k], w);
                fma4(ao, xq[k], w);
            }
            ((float4*)(part + wo * 256))[lane] = am;
            ((float4*)(part + wo * 256 + 128))[lane] = ao;
        }
        __syncthreads();   // join

        // ---- phase 7: memory erase/add (all 512, 2 threads per slot) ----
        {
            const int slot = tid >> 1, q = tid & 1;
            const float wn = wga[slot];
            float* mrow = mem + slot * PITCH + q * 32;
            const float* eq = er + q * 32;
            const float* aq = ad + q * 32;
#pragma unroll 8
            for (int j = 0; j < 32; ++j)
                mrow[j] = mrow[j] * (1.0f - wn * eq[j]) + wn * aq[j];
        }
        cluster_sync_();   // sync C: rv pushes visible everywhere

        // ---- phase 8: out-proj rv-part (k=256..319) on warps 0-3 ----
        if (wi < 4) {
            const int k0 = 256 + wi * 16;
            const int j4 = rk * 128 + (lane << 2);
            const float* wt = g_outT + (size_t)k0 * 512 + j4;
            const float* xm = xin + 192 + k0;
            const float* xq = xot + 192 + k0;
            float4 am = make_float4(0, 0, 0, 0), ao = am;
#pragma unroll
            for (int k = 0; k < 16; ++k) {
                const float4 w = *(const float4*)(wt + (size_t)k * 512);
                fma4(am, xm[k], w);
                fma4(ao, xq[k], w);
            }
            ((float4*)(part + (8 + wi) * 256))[lane] = am;
            ((float4*)(part + (8 + wi) * 256 + 128))[lane] = ao;
        }
        __syncthreads();

        // ---- final reduce + store (12 partial rows), both batches ----
        if (tid < 256) {
            const int bt = tid >> 7, jl = tid & 127;
            float d = 0.0f;
#pragma unroll
            for (int r = 0; r < 12; ++r) d += part[r * 256 + bt * 128 + jl];
            const int gb = (bt == 0) ? gb_m : gb_o;
            const int j = rk * 128 + jl;
            out[((size_t)gb * S_ + t) * V_ + j] = d + obv[j];
        }
        // no trailing sync: next phase-0's __syncthreads orders part reuse,
        // and phase-0 writes touch only xin[0..128)/xot[0..128).
    }
    cluster_sync_();   // no CTA exits while peers may still access its smem
}

extern "C" void kernel_launch(void* const* d_in, const int* in_sizes, int n_in,
                              void* d_out, int out_size)
{
    const int*   x       = (const int*)d_in[0];
    const float* emb     = (const float*)d_in[1];
    const float* W_ih    = (const float*)d_in[2];
    const float* W_hh    = (const float*)d_in[3];
    const float* b_ih    = (const float*)d_in[4];
    const float* b_hh    = (const float*)d_in[5];
    const float* key_W   = (const float*)d_in[6];
    const float* key_b   = (const float*)d_in[7];
    const float* beta_W  = (const float*)d_in[8];
    const float* beta_b  = (const float*)d_in[9];
    const float* gate_W  = (const float*)d_in[10];
    const float* gate_b  = (const float*)d_in[11];
    const float* shift_W = (const float*)d_in[12];
    const float* shift_b = (const float*)d_in[13];
    const float* gamma_W = (const float*)d_in[14];
    const float* gamma_b = (const float*)d_in[15];
    const float* erase_W = (const float*)d_in[16];
    const float* erase_b = (const float*)d_in[17];
    const float* add_W   = (const float*)d_in[18];
    const float* add_b   = (const float*)d_in[19];
    const float* out_W   = (const float*)d_in[20];
    const float* out_b   = (const float*)d_in[21];
    const float* mem_init= (const float*)d_in[22];
    float* out = (float*)d_out;

    prep_kernel<<<256, 512>>>(W_ih, W_hh, key_W, erase_W, add_W,
                              beta_W, gate_W, gamma_W, shift_W, out_W);

    cudaFuncSetAttribute(ntm_kernel, cudaFuncAttributeMaxDynamicSharedMemorySize,
                         (int)SMEM_BYTES);
    ntm_kernel<<<2 * B_, T_, SMEM_BYTES>>>(
        x, emb, b_ih, b_hh,
        key_b, beta_b, gate_b, shift_b, gamma_b, erase_b, add_b, out_b,
        mem_init, out);
}

// round 16
// speedup vs baseline: 1.5007x; 1.5007x over previous
#include <cuda_runtime.h>
#include <math.h>
#include <float.h>

namespace {
constexpr int B_ = 64;    // batch
constexpr int S_ = 128;   // seq len
constexpr int D_ = 128;   // embed dim
constexpr int V_ = 512;   // vocab
constexpr int N_ = 256;   // memory slots
constexpr int M_ = 64;    // memory width
constexpr int PITCH = 65; // smem pitch for mem (bank-conflict-free)
constexpr int T_ = 512;   // threads per CTA (16 warps)

constexpr int SMEM_FLOATS =
    N_ * PITCH   // mem 16640
    + 512        // xin = [emb128 | rv64 | h256 | rv64] (own batch)
    + 1024       // xo[2][512]: other batch x, double-buffered by step parity
    + 4096       // part (local k/j partials)
    + 4096       // pcl  (cross-CTA LSTM partials, by source rank)
    + 1024       // bias (LSTM gate biases)
    + 512        // obv (out biases)
    + 256        // hb (head biases)
    + 256 + 256  // wprev, wga
    + 64 * 3     // keys, er, ad
    + 512        // rvp
    + 16 + 8;    // red, sc
constexpr size_t SMEM_BYTES = SMEM_FLOATS * sizeof(float);
}

// fp32 transposed weights (static device scratch; no allocation)
__device__ float g_lstmT[448 * 1024];  // [k][gate-row]; k = [emb|rv|h]
__device__ float g_headsT[256 * 256];  // [k][ho], ho >= 198 zero-padded
__device__ float g_outT[320 * 512];    // [k][vocab-row]

__global__ void prep_kernel(
    const float* __restrict__ W_ih, const float* __restrict__ W_hh,
    const float* __restrict__ key_W, const float* __restrict__ erase_W,
    const float* __restrict__ add_W, const float* __restrict__ beta_W,
    const float* __restrict__ gate_W, const float* __restrict__ gamma_W,
    const float* __restrict__ shift_W, const float* __restrict__ out_W)
{
    const int stride = blockDim.x * gridDim.x;
    const int t0 = blockIdx.x * blockDim.x + threadIdx.x;
    for (int i = t0; i < 448 * 1024; i += stride) {
        const int k = i >> 10, row = i & 1023;
        g_lstmT[i] = (k < 192) ? W_ih[row * 192 + k] : W_hh[row * 256 + (k - 192)];
    }
    for (int i = t0; i < 256 * 256; i += stride) {
        const int k = i >> 8, ho = i & 255;
        float v = 0.0f;
        if (ho < 64)        v = key_W[ho * 256 + k];
        else if (ho < 128)  v = erase_W[(ho - 64) * 256 + k];
        else if (ho < 192)  v = add_W[(ho - 128) * 256 + k];
        else if (ho == 192) v = beta_W[k];
        else if (ho == 193) v = gate_W[k];
        else if (ho == 194) v = gamma_W[k];
        else if (ho < 198)  v = shift_W[(ho - 195) * 256 + k];
        g_headsT[i] = v;
    }
    for (int i = t0; i < 320 * 512; i += stride) {
        const int k = i >> 9, row = i & 511;
        g_outT[i] = out_W[row * 320 + k];
    }
}

__device__ __forceinline__ float sigm_f(float x) {
    return __fdividef(1.0f, 1.0f + __expf(-x));
}
__device__ __forceinline__ float tanh_f(float x) {
    return __fdividef(2.0f, 1.0f + __expf(-2.0f * x)) - 1.0f;
}
__device__ __forceinline__ float softplus_(float x) { return log1pf(expf(x)); }

__device__ __forceinline__ void fma4(float4& a, float s, const float4 w) {
    a.x = fmaf(s, w.x, a.x); a.y = fmaf(s, w.y, a.y);
    a.z = fmaf(s, w.z, a.z); a.w = fmaf(s, w.w, a.w);
}

__device__ __forceinline__ float rsum(float v) {
#pragma unroll
    for (int o = 16; o; o >>= 1) v += __shfl_xor_sync(0xffffffffu, v, o);
    return v;
}

__device__ __forceinline__ void cluster_sync_() {
    asm volatile("barrier.cluster.arrive.aligned;" ::: "memory");
    asm volatile("barrier.cluster.wait.aligned;" ::: "memory");
}
// store v into CTA `dst` smem at the same offset as local pointer p
__device__ __forceinline__ void st_peer(float* p, unsigned dst, float v) {
    unsigned a = (unsigned)__cvta_generic_to_shared(p);
    unsigned ra;
    asm volatile("mapa.shared::cluster.u32 %0, %1, %2;" : "=r"(ra) : "r"(a), "r"(dst));
    asm volatile("st.shared::cluster.f32 [%0], %1;" :: "r"(ra), "f"(v) : "memory");
}

// Block sum over 512 threads (16 warps). Entry sync protects `red`.
__device__ __forceinline__ float blk_sum(float v, float* red) {
    v = rsum(v);
    __syncthreads();
    if ((threadIdx.x & 31) == 0) red[threadIdx.x >> 5] = v;
    __syncthreads();
    float s = red[0];
#pragma unroll
    for (int i = 1; i < 16; ++i) s += red[i];
    return s;
}

__global__ void __launch_bounds__(T_, 1) __cluster_dims__(4, 1, 1) ntm_kernel(
    const int* __restrict__ x, const float* __restrict__ emb,
    const float* __restrict__ b_ih, const float* __restrict__ b_hh,
    const float* __restrict__ key_b, const float* __restrict__ beta_b,
    const float* __restrict__ gate_b, const float* __restrict__ shift_b,
    const float* __restrict__ gamma_b, const float* __restrict__ erase_b,
    const float* __restrict__ add_b, const float* __restrict__ out_b,
    const float* __restrict__ mem_init, float* __restrict__ out)
{
    extern __shared__ float sm[];
    const int tid = threadIdx.x;
    const int lane = tid & 31;
    const int wi = tid >> 5;            // warp 0..15
    const int bpair = blockIdx.x >> 2;  // cluster index: 2 batch elements
    unsigned rank;
    asm("mov.u32 %0, %%cluster_ctarank;" : "=r"(rank));
    const int rk = (int)rank;           // 0..3
    const int cb = rk >> 1;             // my batch within pair (0/1)
    const unsigned partner = rank ^ 2u; // same j-slice, other batch pair
    const int gb_m = bpair * 2 + cb;        // my global batch
    const int gb_o = bpair * 2 + (1 - cb);  // other global batch

    float* mem   = sm;                 // [N_][PITCH]
    float* xin   = mem + N_ * PITCH;   // 512
    float* xo    = xin + 512;          // [2][512]
    float* part  = xo + 1024;          // 4096
    float* pcl   = part + 4096;        // 4096 [src rank][1024]
    float* bias  = pcl + 4096;         // 1024
    float* obv   = bias + 1024;        // 512
    float* hb    = obv + 512;          // 256
    float* wprev = hb + 256;           // 256
    float* wga   = wprev + N_;         // 256
    float* keys  = wga + N_;           // 64
    float* er    = keys + M_;          // 64
    float* ad    = er + M_;            // 64
    float* rvp   = ad + M_;            // 512
    float* red   = rvp + 512;          // 16
    float* sc    = red + 16;           // 8: beta,gate,gamma,knorm,sh0..2

    // ---- init state & cached biases ----
    for (int i = tid; i < N_ * M_; i += T_)
        mem[(i >> 6) * PITCH + (i & 63)] = mem_init[(size_t)gb_m * N_ * M_ + i];
    bias[tid]       = b_ih[tid]       + b_hh[tid];
    bias[512 + tid] = b_ih[512 + tid] + b_hh[512 + tid];
    obv[tid] = out_b[tid];
    xo[tid] = 0.0f; xo[512 + tid] = 0.0f;
    if (tid < 256) {
        float v = 0.0f;
        if (tid < 64)        v = key_b[tid];
        else if (tid < 128)  v = erase_b[tid - 64];
        else if (tid < 192)  v = add_b[tid - 128];
        else if (tid == 192) v = beta_b[0];
        else if (tid == 193) v = gate_b[0];
        else if (tid == 194) v = gamma_b[0];
        else if (tid < 198)  v = shift_b[tid - 195];
        hb[tid] = v;
    }
    if (tid < 256) { xin[192 + tid] = 0.0f; wprev[tid] = 0.0f; }
    if (tid < 64)  { xin[448 + tid] = 0.0f; xin[128 + tid] = 0.0f; }
    float c_reg = 0.0f;                 // valid for tid < 256
    __syncthreads();
    cluster_sync_();   // xo zero-init complete before any peer traffic

    for (int t = 0; t < S_; ++t) {
        float* xot = xo + ((t & 1) << 9);        // other-batch x, this step
        float* xon = xo + (((t + 1) & 1) << 9);  // other-batch x, next step

        // ---- phase 0: emb loads + own rv copy (local only) ----
        const int tok_m = x[gb_m * S_ + t];
        const int tok_o = x[gb_o * S_ + t];
        if (tid < 128)      { xin[tid] = emb[(size_t)tok_m * D_ + tid];
                              xot[tid] = emb[(size_t)tok_o * D_ + tid]; }
        else if (tid < 192)  xin[tid] = xin[tid + 320];
        __syncthreads();

        // ---- phase 1: LSTM preacts, k-quarter per CTA, both batches ----
        {
            const int jb = wi & 7, ks = wi >> 3;
            const int k0 = rk * 112 + ks * 56;
            const int j = jb * 128 + (lane << 2);
            const float* wt = g_lstmT + (size_t)k0 * 1024 + j;
            const float* xm = xin + k0;
            const float* xq = xot + k0;
            float4 am = make_float4(0, 0, 0, 0), ao = am;
#pragma unroll 4
            for (int k = 0; k < 56; ++k) {
                const float4 w = *(const float4*)(wt + (size_t)k * 1024);
                fma4(am, xm[k], w);
                fma4(ao, xq[k], w);
            }
            ((float4*)(part + ks * 2048 + jb * 128))[lane] = am;
            ((float4*)(part + ks * 2048 + 1024 + jb * 128))[lane] = ao;
        }
        __syncthreads();
#pragma unroll
        for (int i = 0; i < 4; ++i) {
            const int idx = i * 512 + tid;          // 0..2047
            const int bt = idx >> 10, j2 = idx & 1023;
            const float v = part[bt * 1024 + j2] + part[2048 + bt * 1024 + j2];
            const int db = (bt == 0) ? (rk & 2) : ((rk ^ 2) & 2);
            float* dst = &pcl[rk * 1024 + j2];
            if (db == rk)     *dst = v; else st_peer(dst, (unsigned)db, v);
            if (db + 1 == rk) *dst = v; else st_peer(dst, (unsigned)(db + 1), v);
        }
        cluster_sync_();   // sync A: pcl complete everywhere

        // ---- cell update (tid < 256; torch order i,f,g,o) + h push ----
        if (tid < 256) {
            float s0 = 0.f, s1 = 0.f, s2 = 0.f, s3 = 0.f;
#pragma unroll
            for (int r = 0; r < 4; ++r) {
                const float* p = pcl + r * 1024;
                s0 += p[tid]; s1 += p[256 + tid];
                s2 += p[512 + tid]; s3 += p[768 + tid];
            }
            const float ig = sigm_f(s0 + bias[tid]);
            const float fg = sigm_f(s1 + bias[256 + tid]);
            const float gg = tanh_f(s2 + bias[512 + tid]);
            const float og = sigm_f(s3 + bias[768 + tid]);
            c_reg = fg * c_reg + ig * gg;
            const float hv = og * tanh_f(c_reg);
            xin[192 + tid] = hv;
            st_peer(&xot[192 + tid], partner, hv);  // h_t for peer phases 2/8
            st_peer(&xon[192 + tid], partner, hv);  // h_t for peer phase 1 (t+1)
        }
        cluster_sync_();   // sync B1: h_t visible everywhere

        // ---- phase 2: heads, ho-slice per CTA, both batches ----
        {
            const int kg0 = wi * 16;
            float2 am = make_float2(0, 0), ao = am;
            const float* xm = xin + 192 + kg0;
            const float* xq = xot + 192 + kg0;
#pragma unroll
            for (int k = 0; k < 16; ++k) {
                const float2 w = *(const float2*)(g_headsT
                    + (size_t)(kg0 + k) * 256 + rk * 64 + lane * 2);
                am.x = fmaf(xm[k], w.x, am.x); am.y = fmaf(xm[k], w.y, am.y);
                ao.x = fmaf(xq[k], w.x, ao.x); ao.y = fmaf(xq[k], w.y, ao.y);
            }
            ((float2*)(part + wi * 128))[lane] = am;
            ((float2*)(part + wi * 128 + 64))[lane] = ao;
        }
        __syncthreads();
        if (tid < 128) {
            const int bt = tid >> 6, hol = tid & 63;
            float d = 0.0f;
#pragma unroll
            for (int kc = 0; kc < 16; ++kc) d += part[kc * 128 + bt * 64 + hol];
            const int ho = rk * 64 + hol;
            d += hb[ho];
            float* dst = nullptr; float val = 0.0f;
            if (ho < 64)        { dst = &keys[ho];         val = d; }
            else if (ho < 128)  { dst = &er[ho - 64];      val = sigm_f(d); }
            else if (ho < 192)  { dst = &ad[ho - 128];     val = tanh_f(d); }
            else if (ho == 192) { dst = &sc[0];            val = softplus_(d); }
            else if (ho == 193) { dst = &sc[1];            val = sigm_f(d); }
            else if (ho == 194) { dst = &sc[2];            val = 1.0f + softplus_(d); }
            else if (ho < 198)  { dst = &sc[4 + ho - 195]; val = d; }
            if (dst) {
                const int db = (bt == 0) ? (rk & 2) : ((rk ^ 2) & 2);
                if (db == rk)     *dst = val; else st_peer(dst, (unsigned)db, val);
                if (db + 1 == rk) *dst = val; else st_peer(dst, (unsigned)(db + 1), val);
            }
        }
        cluster_sync_();   // sync B: keys/er/ad/sc complete everywhere

        // ---- phase 3: shift softmax (t0) + key norm (warp 1) ----
        if (tid == 0) {
            const float s0 = sc[4], s1 = sc[5], s2 = sc[6];
            const float mx = fmaxf(s0, fmaxf(s1, s2));
            const float e0 = __expf(s0 - mx), e1 = __expf(s1 - mx), e2 = __expf(s2 - mx);
            const float inv = __fdividef(1.0f, e0 + e1 + e2);
            sc[4] = e0 * inv; sc[5] = e1 * inv; sc[6] = e2 * inv;
        } else if (tid >= 32 && tid < 64) {
            const int l = tid - 32;
            float v = keys[l] * keys[l] + keys[l + 32] * keys[l + 32];
#pragma unroll
            for (int o = 16; o; o >>= 1) v += __shfl_xor_sync(0xffffffffu, v, o);
            if (l == 0) sc[3] = fmaxf(sqrtf(v), 1e-12f);
        }
        __syncthreads();

        const float beta = sc[0], gatev = sc[1], gammav = sc[2], knorm = sc[3];
        const float sh0 = sc[4], sh1 = sc[5], sh2 = sc[6];

        // ---- phase 4: content addressing (2 threads per slot; replicated) ----
        {
            const int slot = tid >> 1, q = tid & 1;
            const float* mrow = mem + slot * PITCH + q * 32;
            const float* kq = keys + q * 32;
            float dot = 0.0f, sq = 0.0f;
#pragma unroll 8
            for (int j = 0; j < 32; ++j) {
                const float v = mrow[j];
                dot += v * kq[j];
                sq += v * v;
            }
            dot += __shfl_xor_sync(0xffffffffu, dot, 1);
            sq  += __shfl_xor_sync(0xffffffffu, sq, 1);
            const float sim = __fdividef(dot, fmaxf(sqrtf(sq), 1e-12f) * knorm);
            const float e = __expf(beta * sim);
            const float ssum = blk_sum(q == 0 ? e : 0.0f, red);
            if (q == 0) {
                const float wc = __fdividef(e, ssum);
                wga[slot] = gatev * wc + (1.0f - gatev) * wprev[slot];
            }
        }
        __syncthreads();

        // ---- phase 5: circular conv + sharpening (tid < 256; replicated) ----
        {
            float ws = 0.0f;
            if (tid < 256) {
                const float wt_ = sh0 * wga[(tid + 1) & 255] + sh1 * wga[tid]
                                + sh2 * wga[(tid + 255) & 255];
                ws = __powf(wt_, gammav);
            }
            const float wsum = blk_sum(ws, red);
            if (tid < 256) {
                const float w = __fdividef(ws, wsum);
                wprev[tid] = w;
                wga[tid] = w;
            }
        }
        __syncthreads();

        // ---- phase 6: rv = w @ mem (replicated) ----
        {
            const int m = tid & 63, g = tid >> 6;
            const float* base = mem + (g * 32) * PITCH + m;
            const float* wp = wga + g * 32;
            float s = 0.0f;
#pragma unroll 8
            for (int n = 0; n < 32; ++n) s += wp[n] * base[n * PITCH];
            rvp[g * 64 + m] = s;
        }
        __syncthreads();

        if (tid < 64) {
            float r_ = 0.0f;
#pragma unroll
            for (int g = 0; g < 8; ++g) r_ += rvp[g * 64 + tid];
            xin[448 + tid] = r_;
            st_peer(&xot[448 + tid], partner, r_);  // rv_t for peer phase 8
            st_peer(&xon[128 + tid], partner, r_);  // rv_t for peer LSTM (t+1)
        }

        // ---- phase 7: memory erase/add (2 threads per slot; replicated) ----
        {
            const int slot = tid >> 1, q = tid & 1;
            const float wn = wga[slot];
            float* mrow = mem + slot * PITCH + q * 32;
            const float* eq = er + q * 32;
            const float* aq = ad + q * 32;
#pragma unroll 8
            for (int j = 0; j < 32; ++j)
                mrow[j] = mrow[j] * (1.0f - wn * eq[j]) + wn * aq[j];
        }
        cluster_sync_();   // sync C: rv_t visible everywhere (also local fence)

        // ---- phase 8: output logits, j-slice per CTA, both batches ----
        {
            const int kg0 = wi * 20;
            const int j4 = rk * 128 + (lane << 2);
            const float* wt = g_outT + (size_t)kg0 * 512 + j4;
            const float* xm = xin + 192 + kg0;
            const float* xq = xot + 192 + kg0;
            float4 am = make_float4(0, 0, 0, 0), ao = am;
#pragma unroll 4
            for (int k = 0; k < 20; ++k) {
                const float4 w = *(const float4*)(wt + (size_t)k * 512);
                fma4(am, xm[k], w);
                fma4(ao, xq[k], w);
            }
            ((float4*)(part + wi * 256))[lane] = am;
            ((float4*)(part + wi * 256 + 128))[lane] = ao;
        }
        __syncthreads();
        if (tid < 256) {
            const int bt = tid >> 7, jl = tid & 127;
            float d = 0.0f;
#pragma unroll
            for (int kc = 0; kc < 16; ++kc) d += part[kc * 256 + bt * 128 + jl];
            const int gb = (bt == 0) ? gb_m : gb_o;
            const int j = rk * 128 + jl;
            out[((size_t)gb * S_ + t) * V_ + j] = d + obv[j];
        }
        __syncthreads();
    }
    cluster_sync_();   // no CTA exits while peers may still read/write
}

extern "C" void kernel_launch(void* const* d_in, const int* in_sizes, int n_in,
                              void* d_out, int out_size)
{
    const int*   x       = (const int*)d_in[0];
    const float* emb     = (const float*)d_in[1];
    const float* W_ih    = (const float*)d_in[2];
    const float* W_hh    = (const float*)d_in[3];
    const float* b_ih    = (const float*)d_in[4];
    const float* b_hh    = (const float*)d_in[5];
    const float* key_W   = (const float*)d_in[6];
    const float* key_b   = (const float*)d_in[7];
    const float* beta_W  = (const float*)d_in[8];
    const float* beta_b  = (const float*)d_in[9];
    const float* gate_W  = (const float*)d_in[10];
    const float* gate_b  = (const float*)d_in[11];
    const float* shift_W = (const float*)d_in[12];
    const float* shift_b = (const float*)d_in[13];
    const float* gamma_W = (const float*)d_in[14];
    const float* gamma_b = (const float*)d_in[15];
    const float* erase_W = (const float*)d_in[16];
    const float* erase_b = (const float*)d_in[17];
    const float* add_W   = (const float*)d_in[18];
    const float* add_b   = (const float*)d_in[19];
    const float* out_W   = (const float*)d_in[20];
    const float* out_b   = (const float*)d_in[21];
    const float* mem_init= (const float*)d_in[22];
    float* out = (float*)d_out;

    prep_kernel<<<256, 512>>>(W_ih, W_hh, key_W, erase_W, add_W,
                              beta_W, gate_W, gamma_W, shift_W, out_W);

    cudaFuncSetAttribute(ntm_kernel, cudaFuncAttributeMaxDynamicSharedMemorySize,
                         (int)SMEM_BYTES);
    ntm_kernel<<<2 * B_, T_, SMEM_BYTES>>>(
        x, emb, b_ih, b_hh,
        key_b, beta_b, gate_b, shift_b, gamma_b, erase_b, add_b, out_b,
        mem_init, out);
}